// round 1
// baseline (speedup 1.0000x reference)
#include <cuda_runtime.h>

#define THRESH 0.5f
#define NB 8
#define NA 65536
#define NG 32
#define TPB 256
#define TA 8                 // anchors per thread
#define CHUNK (TPB * TA)     // 2048
#define NCHUNK (NA / CHUNK)  // 32

// Scratch (no allocations allowed)
__device__ unsigned long long g_best[NB * NG];   // packed (iou_bits<<32)|~idx
__device__ unsigned int       g_mask[NB * NA];   // bit g set iff valid && iou>0.5
__device__ float              g_class;
__device__ float              g_coord[NB];
__device__ int                g_cnt[NB];

__global__ void k_init() {
    int t = threadIdx.x;
    if (t < NB * NG) g_best[t] = 0ull;
    if (t == 0) g_class = 0.f;
    if (t < NB) { g_coord[t] = 0.f; g_cnt[t] = 0; }
}

__global__ __launch_bounds__(TPB) void k_pass1(
    const float* __restrict__ anchors,   // [A,4] xyxy
    const float* __restrict__ gt,        // [B,G,4] xywh
    const int*   __restrict__ nobj)      // [B]
{
    const int b    = blockIdx.y;
    const int base = blockIdx.x * CHUNK;
    const int tid  = threadIdx.x;
    const int lane = tid & 31, warp = tid >> 5;

    __shared__ float s_g[5][NG];        // gx1,gy1,gx2,gy2,area_g
    __shared__ float s_iou[8][NG];
    __shared__ unsigned s_idx[8][NG];
    __shared__ int s_n;

    if (tid < NG) {
        float4 q = ((const float4*)gt)[b * NG + tid];   // cx,cy,w,h
        float hx = q.z * 0.5f, hy = q.w * 0.5f;
        float x1 = q.x - hx, y1 = q.y - hy;
        float x2 = q.x + hx, y2 = q.y + hy;
        s_g[0][tid] = x1; s_g[1][tid] = y1;
        s_g[2][tid] = x2; s_g[3][tid] = y2;
        s_g[4][tid] = (x2 - x1) * (y2 - y1);
    }
    if (tid == 0) s_n = nobj[b];
    __syncthreads();
    const int n = s_n;

    float ax1[TA], ay1[TA], ax2[TA], ay2[TA], sa[TA];
    unsigned msk[TA];
#pragma unroll
    for (int k = 0; k < TA; k++) {
        float4 q = ((const float4*)anchors)[base + tid + k * TPB];
        ax1[k] = q.x; ay1[k] = q.y; ax2[k] = q.z; ay2[k] = q.w;
        sa[k] = (q.z - q.x) * (q.w - q.y);
        msk[k] = 0u;
    }

    for (int g = 0; g < n; g++) {
        const float gx1 = s_g[0][g], gy1 = s_g[1][g];
        const float gx2 = s_g[2][g], gy2 = s_g[3][g], sg = s_g[4][g];
        float biou = -1.f; unsigned bidx = 0u;
#pragma unroll
        for (int k = 0; k < TA; k++) {
            float lx = fmaxf(ax1[k], gx1), ly = fmaxf(ay1[k], gy1);
            float rx = fminf(ax2[k], gx2), ry = fminf(ay2[k], gy2);
            float w  = fmaxf(rx - lx, 0.f), h = fmaxf(ry - ly, 0.f);
            float inter = w * h;
            float u = (sa[k] + sg) - inter;
            float iou = __fdiv_rn(inter, u);   // IEEE: bit-matches reference decisions
            if (iou > THRESH) msk[k] |= (1u << g);
            if (iou > biou) { biou = iou; bidx = (unsigned)(base + tid + k * TPB); }
        }
        // warp argmax reduce (first-max tie-break: smaller index wins)
#pragma unroll
        for (int off = 16; off; off >>= 1) {
            float    oi = __shfl_down_sync(0xffffffffu, biou, off);
            unsigned ox = __shfl_down_sync(0xffffffffu, bidx, off);
            if (oi > biou || (oi == biou && ox < bidx)) { biou = oi; bidx = ox; }
        }
        if (lane == 0) { s_iou[warp][g] = biou; s_idx[warp][g] = bidx; }
    }
    __syncthreads();

    if (tid < n) {
        float biou = s_iou[0][tid]; unsigned bidx = s_idx[0][tid];
#pragma unroll
        for (int w = 1; w < 8; w++) {
            float oi = s_iou[w][tid]; unsigned ox = s_idx[w][tid];
            if (oi > biou || (oi == biou && ox < bidx)) { biou = oi; bidx = ox; }
        }
        unsigned long long key =
            ((unsigned long long)__float_as_uint(biou) << 32) | (unsigned)(~bidx);
        atomicMax(&g_best[b * NG + tid], key);
    }

#pragma unroll
    for (int k = 0; k < TA; k++)
        g_mask[b * NA + base + tid + k * TPB] = msk[k];
}

// scatter forced-positive bits (best anchor per valid gt)
__global__ void k_forced(const int* __restrict__ nobj) {
    int t = threadIdx.x;          // 256 = 8*32
    int b = t >> 5, g = t & 31;
    if (g < nobj[b]) {
        unsigned idx = ~(unsigned)(g_best[t] & 0xffffffffull);
        atomicOr(&g_mask[b * NA + idx], 1u << g);
    }
}

__global__ __launch_bounds__(TPB) void k_pass2(
    const float* __restrict__ boxes,   // [B,A,4]
    const float* __restrict__ cls,     // [B,A,2]
    const float* __restrict__ gt)      // [B,G,4]
{
    const int b    = blockIdx.y;
    const int base = blockIdx.x * CHUNK;
    const int tid  = threadIdx.x;
    const int lane = tid & 31, warp = tid >> 5;

    __shared__ float s_g[4][NG];
    if (tid < NG) {
        float4 q = ((const float4*)gt)[b * NG + tid];
        float hx = q.z * 0.5f, hy = q.w * 0.5f;
        s_g[0][tid] = q.x - hx; s_g[1][tid] = q.y - hy;
        s_g[2][tid] = q.x + hx; s_g[3][tid] = q.y + hy;
    }
    __syncthreads();

    float cls_sum = 0.f, crd_sum = 0.f; int cnt = 0;
#pragma unroll
    for (int k = 0; k < TA; k++) {
        int a = base + tid + k * TPB;
        unsigned m = g_mask[b * NA + a];
        float2 c = ((const float2*)cls)[b * NA + a];
        float p  = m ? c.y : c.x;
        float om = 1.f - p;
        cls_sum += om * om * (-logf(p));
        if (m) {
            float4 q = ((const float4*)boxes)[b * NA + a];
            unsigned mm = m;
            while (mm) {
                int g = __ffs(mm) - 1; mm &= mm - 1;
                crd_sum += fabsf(q.x - s_g[0][g]) + fabsf(q.y - s_g[1][g])
                         + fabsf(q.z - s_g[2][g]) + fabsf(q.w - s_g[3][g]);
                cnt++;
            }
        }
    }
#pragma unroll
    for (int off = 16; off; off >>= 1) {
        cls_sum += __shfl_down_sync(0xffffffffu, cls_sum, off);
        crd_sum += __shfl_down_sync(0xffffffffu, crd_sum, off);
        cnt     += __shfl_down_sync(0xffffffffu, cnt, off);
    }
    __shared__ float r_cls[8], r_crd[8];
    __shared__ int r_cnt[8];
    if (lane == 0) { r_cls[warp] = cls_sum; r_crd[warp] = crd_sum; r_cnt[warp] = cnt; }
    __syncthreads();
    if (tid == 0) {
        float tc = 0.f, tr = 0.f; int tn = 0;
#pragma unroll
        for (int w = 0; w < 8; w++) { tc += r_cls[w]; tr += r_crd[w]; tn += r_cnt[w]; }
        atomicAdd(&g_class, tc);
        atomicAdd(&g_coord[b], tr);
        atomicAdd(&g_cnt[b], tn);
    }
}

__global__ void k_fin(float* __restrict__ out) {
    float coord = 0.f;
#pragma unroll
    for (int b = 0; b < NB; b++)
        coord += g_coord[b] / (4.f * (float)g_cnt[b]);
    float class_loss = g_class * (0.01f / 8.f);
    float coord_loss = coord * (1.0f / 8.f);
    out[0] = class_loss + coord_loss;
    out[1] = class_loss;
    out[2] = coord_loss;
}

extern "C" void kernel_launch(void* const* d_in, const int* in_sizes, int n_in,
                              void* d_out, int out_size) {
    const float* boxes   = (const float*)d_in[0];   // [8,65536,4]
    const float* classes = (const float*)d_in[1];   // [8,65536,2]
    const float* anchors = (const float*)d_in[2];   // [65536,4]
    const float* gt      = (const float*)d_in[3];   // [8,32,4]
    const int*   nobj    = (const int*)d_in[4];     // [8]
    float* out = (float*)d_out;

    k_init<<<1, 256>>>();
    k_pass1<<<dim3(NCHUNK, NB), TPB>>>(anchors, gt, nobj);
    k_forced<<<1, 256>>>(nobj);
    k_pass2<<<dim3(NCHUNK, NB), TPB>>>(boxes, classes, gt);
    k_fin<<<1, 1>>>(out);
}

// round 2
// speedup vs baseline: 1.8639x; 1.8639x over previous
#include <cuda_runtime.h>

#define NB 8
#define NA 65536
#define NG 32

// ---- pass1 config ----
#define TPB 256
#define TA 4
#define CHUNK (TPB * TA)      // 1024
#define NCH (NA / CHUNK)      // 64

// ---- pass2 config ----
#define TAC 2
#define CHC (TPB * TAC)       // 512
#define NCHC (NA / CHC)       // 128
#define NBLK_C (NCHC * NB)    // 1024

// Scratch (no allocations allowed)
__device__ float    g_pi[NB * NG * NCH];     // partial best: inter
__device__ float    g_pu[NB * NG * NCH];     // partial best: union
__device__ unsigned g_px[NB * NG * NCH];     // partial best: anchor idx
__device__ unsigned g_mask[NB * NA];         // bit g set iff valid && iou>0.5 (+forced)
__device__ float    g_class;
__device__ float    g_coord[NB];
__device__ int      g_cnt[NB];
__device__ int      g_tick;

// ---------------- Pass 1: IoU mask + per-block argmax partials ----------------
__global__ __launch_bounds__(TPB) void kA(
    const float* __restrict__ anchors,   // [A,4] xyxy
    const float* __restrict__ gt,        // [B,G,4] xywh
    const int*   __restrict__ nobj)      // [B]
{
    const int b    = blockIdx.y;
    const int base = blockIdx.x * CHUNK;
    const int tid  = threadIdx.x;
    const int lane = tid & 31, warp = tid >> 5;

    __shared__ float    s_g[5][NG];          // gx1,gy1,gx2,gy2,area_g
    __shared__ float    s_pi[8][NG], s_pu[8][NG];
    __shared__ unsigned s_px[8][NG];
    __shared__ int      s_n;

    if (tid < NG) {
        float4 q = ((const float4*)gt)[b * NG + tid];   // cx,cy,w,h
        float hx = q.z * 0.5f, hy = q.w * 0.5f;
        float x1 = q.x - hx, y1 = q.y - hy;
        float x2 = q.x + hx, y2 = q.y + hy;
        s_g[0][tid] = x1; s_g[1][tid] = y1;
        s_g[2][tid] = x2; s_g[3][tid] = y2;
        s_g[4][tid] = (x2 - x1) * (y2 - y1);
    }
    if (tid == 0) s_n = nobj[b];
    __syncthreads();
    const int n = s_n;

    float ax1[TA], ay1[TA], ax2[TA], ay2[TA], sa[TA];
    unsigned msk[TA];
#pragma unroll
    for (int k = 0; k < TA; k++) {
        float4 q = ((const float4*)anchors)[base + tid + k * TPB];
        ax1[k] = q.x; ay1[k] = q.y; ax2[k] = q.z; ay2[k] = q.w;
        sa[k] = (q.z - q.x) * (q.w - q.y);
        msk[k] = 0u;
    }

    for (int g = 0; g < n; g++) {
        const float gx1 = s_g[0][g], gy1 = s_g[1][g];
        const float gx2 = s_g[2][g], gy2 = s_g[3][g], sg = s_g[4][g];
        const unsigned bit = 1u << g;
        // running best as (inter, union) pair; ratio compare via cross-multiply
        float bi = -1.f, bu = 1.f; unsigned bx = base + tid;
#pragma unroll
        for (int k = 0; k < TA; k++) {
            float lx = fmaxf(ax1[k], gx1), ly = fmaxf(ay1[k], gy1);
            float rx = fminf(ax2[k], gx2), ry = fminf(ay2[k], gy2);
            float w  = fmaxf(rx - lx, 0.f), h = fmaxf(ry - ly, 0.f);
            float inter = w * h;
            float u = (sa[k] + sg) - inter;
            // exact sign of (inter - 0.5*u): single-rounded FFMA, 0.5*u exact
            if (fmaf(-0.5f, u, inter) > 0.f) msk[k] |= bit;
            // iou_k > iou_best  <=>  inter*bu > bi*u  (u,bu > 0)
            if (inter * bu > bi * u) {
                bi = inter; bu = u; bx = (unsigned)(base + tid + k * TPB);
            }
        }
        // warp argmax reduce; first-max tie-break = smaller anchor index
#pragma unroll
        for (int off = 16; off; off >>= 1) {
            float    oi = __shfl_down_sync(0xffffffffu, bi, off);
            float    ou = __shfl_down_sync(0xffffffffu, bu, off);
            unsigned ox = __shfl_down_sync(0xffffffffu, bx, off);
            float a = oi * bu, c = bi * ou;
            if (a > c || (a == c && ox < bx)) { bi = oi; bu = ou; bx = ox; }
        }
        if (lane == 0) { s_pi[warp][g] = bi; s_pu[warp][g] = bu; s_px[warp][g] = bx; }
    }
    __syncthreads();

    if (tid < n) {   // one thread per valid g reduces the 8 warp partials
        float bi = s_pi[0][tid], bu = s_pu[0][tid]; unsigned bx = s_px[0][tid];
#pragma unroll
        for (int w = 1; w < 8; w++) {
            float oi = s_pi[w][tid], ou = s_pu[w][tid]; unsigned ox = s_px[w][tid];
            float a = oi * bu, c = bi * ou;
            if (a > c || (a == c && ox < bx)) { bi = oi; bu = ou; bx = ox; }
        }
        int p = (b * NG + tid) * NCH + blockIdx.x;
        g_pi[p] = bi; g_pu[p] = bu; g_px[p] = bx;
    }

#pragma unroll
    for (int k = 0; k < TA; k++)
        g_mask[b * NA + base + tid + k * TPB] = msk[k];
}

// ------- Middle: reduce partials -> forced bits; zero accumulators -------
__global__ void kB(const int* __restrict__ nobj) {
    const int b = blockIdx.x;            // 8 blocks x 256 threads
    const int t = threadIdx.x;
    if (b == 0) {
        if (t == 0) { g_class = 0.f; g_tick = 0; }
        if (t < NB) { g_coord[t] = 0.f; g_cnt[t] = 0; }
    }
    const int g = t >> 3, s = t & 7;     // 8 threads per g
    float bi = -1.f, bu = 1.f; unsigned bx = 0u;
    const int base = (b * NG + g) * NCH;
    for (int c = s * 8; c < s * 8 + 8; c++) {
        float oi = g_pi[base + c], ou = g_pu[base + c]; unsigned ox = g_px[base + c];
        float a = oi * bu, d = bi * ou;
        if (a > d || (a == d && ox < bx)) { bi = oi; bu = ou; bx = ox; }
    }
#pragma unroll
    for (int off = 4; off; off >>= 1) {
        float    oi = __shfl_down_sync(0xffffffffu, bi, off, 8);
        float    ou = __shfl_down_sync(0xffffffffu, bu, off, 8);
        unsigned ox = __shfl_down_sync(0xffffffffu, bx, off, 8);
        float a = oi * bu, d = bi * ou;
        if (a > d || (a == d && ox < bx)) { bi = oi; bu = ou; bx = ox; }
    }
    if (s == 0 && g < nobj[b])
        atomicOr(&g_mask[b * NA + bx], 1u << g);
}

// ---------------- Pass 2: class + coord losses, ticketed finalize ----------------
__global__ __launch_bounds__(TPB) void kC(
    const float* __restrict__ boxes,   // [B,A,4]
    const float* __restrict__ cls,     // [B,A,2]
    const float* __restrict__ gt,      // [B,G,4]
    float* __restrict__ out)
{
    const int b    = blockIdx.y;
    const int base = blockIdx.x * CHC;
    const int tid  = threadIdx.x;
    const int lane = tid & 31, warp = tid >> 5;

    __shared__ float s_g[4][NG];
    if (tid < NG) {
        float4 q = ((const float4*)gt)[b * NG + tid];
        float hx = q.z * 0.5f, hy = q.w * 0.5f;
        s_g[0][tid] = q.x - hx; s_g[1][tid] = q.y - hy;
        s_g[2][tid] = q.x + hx; s_g[3][tid] = q.y + hy;
    }
    __syncthreads();

    const int a0 = base + tid * TAC;
    uint2  m2 = *(const uint2*)&g_mask[b * NA + a0];
    float4 c2 = ((const float4*)cls)[(b * NA + a0) >> 1];

    float p0 = m2.x ? c2.y : c2.x;
    float p1 = m2.y ? c2.w : c2.z;
    float o0 = 1.f - p0, o1 = 1.f - p1;
    float cls_sum = o0 * o0 * (-logf(p0)) + o1 * o1 * (-logf(p1));

    float crd_sum = 0.f; int cnt = 0;
#pragma unroll
    for (int k = 0; k < TAC; k++) {
        unsigned m = k ? m2.y : m2.x;
        if (m) {
            float4 q = ((const float4*)boxes)[b * NA + a0 + k];
            do {
                int g = __ffs(m) - 1; m &= m - 1;
                crd_sum += fabsf(q.x - s_g[0][g]) + fabsf(q.y - s_g[1][g])
                         + fabsf(q.z - s_g[2][g]) + fabsf(q.w - s_g[3][g]);
                cnt++;
            } while (m);
        }
    }
#pragma unroll
    for (int off = 16; off; off >>= 1) {
        cls_sum += __shfl_down_sync(0xffffffffu, cls_sum, off);
        crd_sum += __shfl_down_sync(0xffffffffu, crd_sum, off);
        cnt     += __shfl_down_sync(0xffffffffu, cnt, off);
    }
    __shared__ float r_cls[8], r_crd[8];
    __shared__ int   r_cnt[8];
    if (lane == 0) { r_cls[warp] = cls_sum; r_crd[warp] = crd_sum; r_cnt[warp] = cnt; }
    __syncthreads();
    if (tid == 0) {
        float tc = 0.f, tr = 0.f; int tn = 0;
#pragma unroll
        for (int w = 0; w < 8; w++) { tc += r_cls[w]; tr += r_crd[w]; tn += r_cnt[w]; }
        atomicAdd(&g_class, tc);
        atomicAdd(&g_coord[b], tr);
        atomicAdd(&g_cnt[b], tn);
        __threadfence();
        if (atomicAdd(&g_tick, 1) == NBLK_C - 1) {   // last block finalizes
            __threadfence();
            float coord = 0.f;
#pragma unroll
            for (int bb = 0; bb < NB; bb++) {
                float c  = *(volatile float*)&g_coord[bb];
                int   nn = *(volatile int*)&g_cnt[bb];
                coord += c / (4.f * (float)nn);
            }
            float cl = (*(volatile float*)&g_class) * (0.01f / 8.f);
            float co = coord * (1.0f / 8.f);
            out[0] = cl + co;
            out[1] = cl;
            out[2] = co;
        }
    }
}

extern "C" void kernel_launch(void* const* d_in, const int* in_sizes, int n_in,
                              void* d_out, int out_size) {
    const float* boxes   = (const float*)d_in[0];   // [8,65536,4]
    const float* classes = (const float*)d_in[1];   // [8,65536,2]
    const float* anchors = (const float*)d_in[2];   // [65536,4]
    const float* gt      = (const float*)d_in[3];   // [8,32,4]
    const int*   nobj    = (const int*)d_in[4];     // [8]
    float* out = (float*)d_out;

    kA<<<dim3(NCH, NB), TPB>>>(anchors, gt, nobj);
    kB<<<NB, 256>>>(nobj);
    kC<<<dim3(NCHC, NB), TPB>>>(boxes, classes, gt, out);
}

// round 4
// speedup vs baseline: 1.8783x; 1.0077x over previous
#include <cuda_runtime.h>

#define NB 8
#define NA 65536
#define NG 32

// ---- pass1 (kA) config: lanes = gts, anchors serial ----
#define AW   128               // anchors per warp
#define WPB  8                 // warps per block
#define ABLK (AW * WPB)        // 1024 anchors per block
#define NCH  (NA / ABLK)       // 64 blocks per batch

// ---- pass2 (kC) config ----
#define TPB 256
#define TAC 2
#define CHC (TPB * TAC)        // 512
#define NCHC (NA / CHC)        // 128
#define NBLK_C (NCHC * NB)     // 1024

// Scratch (no allocations allowed)
__device__ float    g_pi[NB * NG * NCH];     // partial best: inter
__device__ float    g_pu[NB * NG * NCH];     // partial best: union
__device__ unsigned g_px[NB * NG * NCH];     // partial best: anchor idx
__device__ unsigned g_mask[NB * NA];         // bit g set iff valid && iou>0.5 (+forced)
__device__ float    g_class;
__device__ float    g_coord[NB];
__device__ int      g_cnt[NB];
__device__ int      g_tick;

// ------------- Pass 1: lanes=g; ballot mask + serial argmax -------------
__global__ __launch_bounds__(256) void kA(
    const float* __restrict__ anchors,   // [A,4] xyxy
    const float* __restrict__ gt,        // [B,G,4] xywh
    const int*   __restrict__ nobj)      // [B]
{
    const int b    = blockIdx.y;
    const int tid  = threadIdx.x;
    const int lane = tid & 31, warp = tid >> 5;
    const int a_base = blockIdx.x * ABLK + warp * AW;

    // per-lane gt constants (lane == g)
    float gx1, gy1, gx2, gy2, sg;
    {
        const int n = nobj[b];
        float4 q = ((const float4*)gt)[b * NG + lane];   // cx,cy,w,h
        float hx = q.z * 0.5f, hy = q.w * 0.5f;
        gx1 = q.x - hx; gy1 = q.y - hy;
        gx2 = q.x + hx; gy2 = q.y + hy;
        sg  = (gx2 - gx1) * (gy2 - gy1);
        if (lane >= n) {           // sentinel: zero overlap with any anchor
            gx1 = 3e9f; gx2 = 3e9f; gy1 = 0.f; gy2 = 1.f; sg = 0.f;
        }
    }

    // running per-lane best over this warp's anchors (exact ratio via (inter,u))
    float bi = 0.f, bu = 1.f;
    unsigned bx = (unsigned)a_base;

    for (int a0 = a_base; a0 < a_base + AW; a0 += 4) {
        unsigned mw0, mw1, mw2, mw3;
#pragma unroll
        for (int k = 0; k < 4; k++) {
            float4 q = __ldg(((const float4*)anchors) + a0 + k);
            float sa = (q.z - q.x) * (q.w - q.y);
            float lx = fmaxf(q.x, gx1), ly = fmaxf(q.y, gy1);
            float rx = fminf(q.z, gx2), ry = fminf(q.w, gy2);
            float w  = fmaxf(rx - lx, 0.f), h = fmaxf(ry - ly, 0.f);
            float inter = w * h;
            float u = (sa + sg) - inter;
            // exact sign of inter - 0.5u (single rounding; 0.5u exact)
            bool pos = fmaf(-0.5f, u, inter) > 0.f;
            unsigned bal = __ballot_sync(0xffffffffu, pos);
            if (k == 0) mw0 = bal; else if (k == 1) mw1 = bal;
            else if (k == 2) mw2 = bal; else mw3 = bal;
            // iou > best  <=>  inter*bu > bi*u  (u,bu > 0); strict > keeps
            // earliest (smallest) anchor index == jnp.argmax tie-break
            if (inter * bu > bi * u) { bi = inter; bu = u; bx = (unsigned)(a0 + k); }
        }
        if (lane == 0)
            *(uint4*)&g_mask[b * NA + a0] = make_uint4(mw0, mw1, mw2, mw3);
    }

    // block-level argmax reduce (8 warps, anchor-range ordered)
    __shared__ float    s_bi[WPB][NG], s_bu[WPB][NG];
    __shared__ unsigned s_bx[WPB][NG];
    s_bi[warp][lane] = bi; s_bu[warp][lane] = bu; s_bx[warp][lane] = bx;
    __syncthreads();
    if (tid < NG) {
        float Bi = s_bi[0][tid], Bu = s_bu[0][tid];
        unsigned Bx = s_bx[0][tid];
#pragma unroll
        for (int w = 1; w < WPB; w++) {
            float oi = s_bi[w][tid], ou = s_bu[w][tid];
            unsigned ox = s_bx[w][tid];
            float A = oi * Bu, C = Bi * ou;
            if (A > C || (A == C && ox < Bx)) { Bi = oi; Bu = ou; Bx = ox; }
        }
        int p = (b * NG + tid) * NCH + blockIdx.x;
        g_pi[p] = Bi; g_pu[p] = Bu; g_px[p] = Bx;
    }
}

// ------- Middle: reduce partials -> forced bits; zero accumulators -------
__global__ void kB(const int* __restrict__ nobj) {
    const int b = blockIdx.x;            // 8 blocks x 256 threads
    const int t = threadIdx.x;
    if (b == 0) {
        if (t == 0) { g_class = 0.f; g_tick = 0; }
        if (t < NB) { g_coord[t] = 0.f; g_cnt[t] = 0; }
    }
    const int g = t >> 3, s = t & 7;     // 8 threads per g
    float bi = 0.f, bu = 1.f; unsigned bx = 0xffffffffu;
    const int base = (b * NG + g) * NCH;
    for (int c = s * 8; c < s * 8 + 8; c++) {
        float oi = g_pi[base + c], ou = g_pu[base + c]; unsigned ox = g_px[base + c];
        float a = oi * bu, d = bi * ou;
        if (a > d || (a == d && ox < bx)) { bi = oi; bu = ou; bx = ox; }
    }
#pragma unroll
    for (int off = 4; off; off >>= 1) {
        float    oi = __shfl_down_sync(0xffffffffu, bi, off, 8);
        float    ou = __shfl_down_sync(0xffffffffu, bu, off, 8);
        unsigned ox = __shfl_down_sync(0xffffffffu, bx, off, 8);
        float a = oi * bu, d = bi * ou;
        if (a > d || (a == d && ox < bx)) { bi = oi; bu = ou; bx = ox; }
    }
    if (s == 0 && g < nobj[b])
        atomicOr(&g_mask[b * NA + bx], 1u << g);
}

// -------- Pass 2: class + coord losses, ticketed finalize --------
__global__ __launch_bounds__(TPB) void kC(
    const float* __restrict__ boxes,   // [B,A,4]
    const float* __restrict__ cls,     // [B,A,2]
    const float* __restrict__ gt,      // [B,G,4]
    float* __restrict__ out)
{
    const int b    = blockIdx.y;
    const int base = blockIdx.x * CHC;
    const int tid  = threadIdx.x;
    const int lane = tid & 31, warp = tid >> 5;

    __shared__ float s_g[4][NG];
    if (tid < NG) {
        float4 q = ((const float4*)gt)[b * NG + tid];
        float hx = q.z * 0.5f, hy = q.w * 0.5f;
        s_g[0][tid] = q.x - hx; s_g[1][tid] = q.y - hy;
        s_g[2][tid] = q.x + hx; s_g[3][tid] = q.y + hy;
    }
    __syncthreads();

    const int a0 = base + tid * TAC;
    uint2  m2 = *(const uint2*)&g_mask[b * NA + a0];
    float4 c2 = ((const float4*)cls)[(b * NA + a0) >> 1];

    float p0 = m2.x ? c2.y : c2.x;
    float p1 = m2.y ? c2.w : c2.z;
    float o0 = 1.f - p0, o1 = 1.f - p1;
    float cls_sum = o0 * o0 * (-logf(p0)) + o1 * o1 * (-logf(p1));

    float crd_sum = 0.f; int cnt = 0;
#pragma unroll
    for (int k = 0; k < TAC; k++) {
        unsigned m = k ? m2.y : m2.x;
        if (m) {
            float4 q = ((const float4*)boxes)[b * NA + a0 + k];
            do {
                int g = __ffs(m) - 1; m &= m - 1;
                crd_sum += fabsf(q.x - s_g[0][g]) + fabsf(q.y - s_g[1][g])
                         + fabsf(q.z - s_g[2][g]) + fabsf(q.w - s_g[3][g]);
                cnt++;
            } while (m);
        }
    }
#pragma unroll
    for (int off = 16; off; off >>= 1) {
        cls_sum += __shfl_down_sync(0xffffffffu, cls_sum, off);
        crd_sum += __shfl_down_sync(0xffffffffu, crd_sum, off);
        cnt     += __shfl_down_sync(0xffffffffu, cnt, off);
    }
    __shared__ float r_cls[8], r_crd[8];
    __shared__ int   r_cnt[8];
    if (lane == 0) { r_cls[warp] = cls_sum; r_crd[warp] = crd_sum; r_cnt[warp] = cnt; }
    __syncthreads();
    if (tid == 0) {
        float tc = 0.f, tr = 0.f; int tn = 0;
#pragma unroll
        for (int w = 0; w < 8; w++) { tc += r_cls[w]; tr += r_crd[w]; tn += r_cnt[w]; }
        atomicAdd(&g_class, tc);
        atomicAdd(&g_coord[b], tr);
        atomicAdd(&g_cnt[b], tn);
        __threadfence();
        if (atomicAdd(&g_tick, 1) == NBLK_C - 1) {   // last block finalizes
            __threadfence();
            float coord = 0.f;
#pragma unroll
            for (int bb = 0; bb < NB; bb++) {
                float c  = *(volatile float*)&g_coord[bb];
                int   nn = *(volatile int*)&g_cnt[bb];
                coord += c / (4.f * (float)nn);
            }
            float cl = (*(volatile float*)&g_class) * (0.01f / 8.f);
            float co = coord * (1.0f / 8.f);
            out[0] = cl + co;
            out[1] = cl;
            out[2] = co;
        }
    }
}

extern "C" void kernel_launch(void* const* d_in, const int* in_sizes, int n_in,
                              void* d_out, int out_size) {
    const float* boxes   = (const float*)d_in[0];   // [8,65536,4]
    const float* classes = (const float*)d_in[1];   // [8,65536,2]
    const float* anchors = (const float*)d_in[2];   // [65536,4]
    const float* gt      = (const float*)d_in[3];   // [8,32,4]
    const int*   nobj    = (const int*)d_in[4];     // [8]
    float* out = (float*)d_out;

    kA<<<dim3(NCH, NB), 256>>>(anchors, gt, nobj);
    kB<<<NB, 256>>>(nobj);
    kC<<<dim3(NCHC, NB), TPB>>>(boxes, classes, gt, out);
}